// round 7
// baseline (speedup 1.0000x reference)
#include <cuda_runtime.h>
#include <cuda_fp16.h>
#include <cstdint>
#include <math.h>

#define CIN 64
#define COUT 256
#define DD 31
#define HH 96
#define WW 96
#define HW (HH*WW)
#define DHW (DD*HW)
#define EPS 1e-5f

#define BH 8
#define BW 32

// padded transposed x: [33][98][104][64] fp16, swizzle baked (key = w&7)
#define XT_D 33
#define XT_H 98
#define XT_W 104
#define XT_ROWS (XT_D*XT_H*XT_W)
__device__ __half g_xt[(size_t)XT_ROWS * 64];

__device__ float  g_gates[(size_t)COUT * DHW];   // activated gates [cout][d][h][w]
__device__ __half g_wth[27 * COUT * CIN];        // [tap][cout][cin] fp16, swizzle baked (key = cout&7)

// smem layout: A 4-stage buffer 4x16KB, then B region
#define SMA_BYTES 16384
#define NSTAGE 4
#define SMB_OFF (NSTAGE*SMA_BYTES)
#define B_ROW_BASE 7
#define B_RUN_STRIDE 40
#define B_PLANE_ROWS (10*B_RUN_STRIDE)
#define B_ROWS (B_ROW_BASE + 29*B_RUN_STRIDE + 34)   // 1201
#define SMEM_TOTAL (SMB_OFF + B_ROWS*128)            // 219264

__device__ __forceinline__ uint32_t cvta_s(const void* p) {
    uint32_t a;
    asm("{ .reg .u64 t; cvta.to.shared.u64 t, %1; cvt.u32.u64 %0, t; }" : "=r"(a) : "l"(p));
    return a;
}
__device__ __forceinline__ float fast_tanh(float x) {
    float y; asm("tanh.approx.f32 %0, %1;" : "=f"(y) : "f"(x)); return y;
}
__device__ __forceinline__ void ldsm_x4(uint32_t& r0, uint32_t& r1, uint32_t& r2, uint32_t& r3,
                                        uint32_t addr) {
    asm volatile("ldmatrix.sync.aligned.m8n8.x4.shared.b16 {%0,%1,%2,%3}, [%4];"
        : "=r"(r0), "=r"(r1), "=r"(r2), "=r"(r3) : "r"(addr));
}
#define MBAR_INIT(mbar, count) \
    asm volatile("mbarrier.init.shared.b64 [%0], %1;" :: "r"((uint32_t)(mbar)), "r"((uint32_t)(count)) : "memory")
#define MBAR_EXPECT_TX(mbar, bytes) \
    asm volatile("mbarrier.arrive.expect_tx.shared.b64 _, [%0], %1;" \
        :: "r"((uint32_t)(mbar)), "r"((uint32_t)(bytes)) : "memory")
#define MBAR_WAIT(mbar, parity) do { \
    uint32_t _m = (uint32_t)(mbar); uint32_t _p = (uint32_t)(parity); uint32_t _done; \
    asm volatile("{\n\t.reg .pred p;\n\tmbarrier.try_wait.parity.acquire.cta.shared::cta.b64 p, [%1], %2;\n\tselp.b32 %0, 1, 0, p;\n\t}" \
        : "=r"(_done) : "r"(_m), "r"(_p) : "memory"); \
    if (!_done) { \
        asm volatile("{\n\t.reg .pred P1;\n\tWL_%=:\n\tmbarrier.try_wait.parity.acquire.cta.shared::cta.b64 P1, [%0], %1, 0x989680;\n\t@P1 bra.uni WD_%=;\n\tbra.uni WL_%=;\n\tWD_%=:\n\t}" \
            :: "r"(_m), "r"(_p) : "memory"); \
    } } while (0)
#define BULK_G2S(dst, src, bytes, mbar) \
    asm volatile("cp.async.bulk.shared::cluster.global.mbarrier::complete_tx::bytes [%0], [%1], %2, [%3];" \
        :: "r"((uint32_t)(dst)), "l"(src), "r"((uint32_t)(bytes)), "r"((uint32_t)(mbar)) : "memory")

// ---------------- pre-pass kernels ----------------
__global__ void zero_xt_kernel() {
    size_t i = (size_t)blockIdx.x * blockDim.x + threadIdx.x;
    float4* p = reinterpret_cast<float4*>(g_xt);
    if (i < ((size_t)XT_ROWS * 128) / 16) p[i] = make_float4(0.f, 0.f, 0.f, 0.f);
}

// x[ci][d][h][w] f32 -> g_xt[(d+1)][(h+1)][(w+1)][ci] fp16, chunks swizzled by (w&7)
__global__ void transpose_x_kernel(const float* __restrict__ x) {
    const int d = blockIdx.y, h = blockIdx.x;
    const int w = threadIdx.x;
    if (w >= WW) return;
    const float* src = x + (size_t)d * HW + h * WW + w;
    uint32_t pk[32];
#pragma unroll
    for (int j = 0; j < 32; ++j) {
        float v0 = src[(size_t)(2 * j) * DHW];
        float v1 = src[(size_t)(2 * j + 1) * DHW];
        __half2 h2 = __float22half2_rn(make_float2(v0, v1));
        pk[j] = *reinterpret_cast<uint32_t*>(&h2);
    }
    char* dst = (char*)g_xt + ((size_t)((d + 1) * XT_H + (h + 1)) * XT_W + (w + 1)) * 128;
    const int key = w & 7;
#pragma unroll
    for (int c = 0; c < 8; ++c) {
        uint4 q = make_uint4(pk[c * 4], pk[c * 4 + 1], pk[c * 4 + 2], pk[c * 4 + 3]);
        *reinterpret_cast<uint4*>(dst + ((c ^ key) << 4)) = q;
    }
}

// w[cout][cin][27] -> g_wth[tap][cout][...swizzled cin...]
__global__ void repack_kernel(const float* __restrict__ w) {
    int id = blockIdx.x * blockDim.x + threadIdx.x;
    if (id >= COUT * CIN) return;
    int cout = id >> 6, cin = id & 63;
    const float* src = w + (size_t)id * 27;
    const int c = cin >> 3, key = cout & 7;
    const int pos = ((c ^ key) << 3) + (cin & 7);
#pragma unroll
    for (int t = 0; t < 27; ++t)
        g_wth[((size_t)t * COUT + cout) * 64 + pos] = __float2half_rn(src[t]);
}

// ---------------- conv + BN + activation ----------------
__global__ __launch_bounds__(256, 1)
void conv_mma_kernel(const float* __restrict__ gamma, const float* __restrict__ beta,
                     const float* __restrict__ mean, const float* __restrict__ var)
{
    extern __shared__ __align__(128) char smem[];
    __shared__ __align__(8) uint64_t mbars[NSTAGE + 3];   // A0..A3, B0..B2
    const uint32_t smA_u = cvta_s(smem);
    const uint32_t smB_u = smA_u + SMB_OFF;
    uint32_t mbA[NSTAGE], mbB[3];
#pragma unroll
    for (int i = 0; i < NSTAGE; ++i) mbA[i] = cvta_s(&mbars[i]);
#pragma unroll
    for (int i = 0; i < 3; ++i) mbB[i] = cvta_s(&mbars[NSTAGE + i]);

    const int tid = threadIdx.x, wid = tid >> 5, lane = tid & 31;
    const int d = blockIdx.y;
    const int coutBase = blockIdx.z * 128;
    const int hBase = (blockIdx.x / 3) * BH, wBase = (blockIdx.x % 3) * BW;

    const int warpM = (wid >> 2) * 64, warpN = (wid & 3) * 64;
    const int mr = lane >> 2, nc = lane & 3;
    const int matsel = lane >> 3, rl = lane & 7;
    const int mhalf = matsel & 1, khalf = matsel >> 1;

    int rowA[4], rowA7[4];
#pragma unroll
    for (int f = 0; f < 4; ++f) {
        rowA[f] = warpM + 16 * f + mhalf * 8 + rl;
        rowA7[f] = rowA[f] & 7;
    }
    int browB[4];
#pragma unroll
    for (int g2 = 0; g2 < 4; ++g2) {
        int n = warpN + g2 * 16 + mhalf * 8 + rl;
        browB[g2] = B_ROW_BASE + (n >> 5) * B_RUN_STRIDE + (n & 31);
    }

    if (tid == 0) {
#pragma unroll
        for (int i = 0; i < NSTAGE; ++i) MBAR_INIT(mbA[i], 1);
#pragma unroll
        for (int i = 0; i < 3; ++i) MBAR_INIT(mbB[i], 1);
    }
    __syncthreads();

    if (tid == 0) {
        // ---- B plane 0 first (compute can start on it), then A 0..2, then planes 1,2
        {
            const int dz = d;   // padded plane index for kd=0
            MBAR_EXPECT_TX(mbB[0], 10u * 4352u);
            for (int he = 0; he < 10; ++he) {
                const char* src = (const char*)g_xt
                    + ((size_t)(dz * XT_H + hBase + he) * XT_W + wBase) * 128;
                BULK_G2S(smB_u + (B_ROW_BASE + he * B_RUN_STRIDE) * 128, src, 4352u, mbB[0]);
            }
        }
#pragma unroll
        for (int t = 0; t < 3; ++t) {
            MBAR_EXPECT_TX(mbA[t], SMA_BYTES);
            BULK_G2S(smA_u + t * SMA_BYTES,
                     (const char*)g_wth + ((size_t)t * COUT + coutBase) * 128,
                     SMA_BYTES, mbA[t]);
        }
#pragma unroll
        for (int dzl = 1; dzl < 3; ++dzl) {
            const int dz = d + dzl;
            MBAR_EXPECT_TX(mbB[dzl], 10u * 4352u);
            for (int he = 0; he < 10; ++he) {
                const char* src = (const char*)g_xt
                    + ((size_t)(dz * XT_H + hBase + he) * XT_W + wBase) * 128;
                const int ri = dzl * 10 + he;
                BULK_G2S(smB_u + (B_ROW_BASE + ri * B_RUN_STRIDE) * 128, src, 4352u, mbB[dzl]);
            }
        }
    }

    float acc[4][8][4];
#pragma unroll
    for (int f = 0; f < 4; ++f)
#pragma unroll
        for (int g = 0; g < 8; ++g)
#pragma unroll
            for (int c = 0; c < 4; ++c) acc[f][g][c] = 0.0f;

    for (int tap = 0; tap < 27; ++tap) {
        if (tap > 0) __syncthreads();   // all warps done with tap-1 -> buf (tap+3)%4 free
        if (tid == 0 && tap + 3 < 27) {
            const int nt = tap + 3, buf = nt & (NSTAGE - 1);
            MBAR_EXPECT_TX(mbA[buf], SMA_BYTES);
            BULK_G2S(smA_u + buf * SMA_BYTES,
                     (const char*)g_wth + ((size_t)nt * COUT + coutBase) * 128,
                     SMA_BYTES, mbA[buf]);
        }
        const int kd = tap / 9, kh = (tap / 3) % 3, kw = tap % 3;
        if (kh == 0 && kw == 0) { MBAR_WAIT(mbB[kd], 0); }
        MBAR_WAIT(mbA[tap & (NSTAGE - 1)], (tap >> 2) & 1);

        const uint32_t Abase = smA_u + (tap & (NSTAGE - 1)) * SMA_BYTES;
        const int broff = kd * B_PLANE_ROWS + kh * B_RUN_STRIDE + kw;
#pragma unroll
        for (int s = 0; s < 4; ++s) {
            const int col16 = s * 2 + khalf;
            uint32_t a[4][4];
#pragma unroll
            for (int f = 0; f < 4; ++f) {
                ldsm_x4(a[f][0], a[f][1], a[f][2], a[f][3],
                        Abase + rowA[f] * 128 + ((col16 ^ rowA7[f]) << 4));
            }
            uint32_t b[8][2];
#pragma unroll
            for (int g2 = 0; g2 < 4; ++g2) {
                const int brow = browB[g2] + broff;
                ldsm_x4(b[2 * g2][0], b[2 * g2 + 1][0],
                        b[2 * g2][1], b[2 * g2 + 1][1],
                        smB_u + brow * 128 + ((col16 ^ (brow & 7)) << 4));
            }
#pragma unroll
            for (int f = 0; f < 4; ++f)
#pragma unroll
                for (int g = 0; g < 8; ++g) {
                    asm volatile(
                        "mma.sync.aligned.m16n8k16.row.col.f32.f16.f16.f32 "
                        "{%0,%1,%2,%3}, {%4,%5,%6,%7}, {%8,%9}, {%0,%1,%2,%3};"
                        : "+f"(acc[f][g][0]), "+f"(acc[f][g][1]),
                          "+f"(acc[f][g][2]), "+f"(acc[f][g][3])
                        : "r"(a[f][0]), "r"(a[f][1]), "r"(a[f][2]), "r"(a[f][3]),
                          "r"(b[g][0]), "r"(b[g][1]));
                }
        }
    }

    // ---- epilogue: BN + activation + STG (float2)
#pragma unroll
    for (int f = 0; f < 4; ++f)
#pragma unroll
        for (int r = 0; r < 2; ++r) {
            const int cg = coutBase + warpM + 16 * f + 8 * r + mr;
            const float s = gamma[cg] * rsqrtf(var[cg] + EPS);
            const float sh = beta[cg] - mean[cg] * s;
            const int gt = cg >> 6;
            const bool sg = (gt == 1) || (gt == 2);
            float* orow = g_gates + (size_t)cg * DHW + (size_t)d * HW;
#pragma unroll
            for (int g = 0; g < 8; ++g) {
                const int n0 = warpN + 8 * g + 2 * nc;
                const int h2 = n0 >> 5, w2 = n0 & 31;
                float v0 = acc[f][g][2 * r + 0] * s + sh;
                float v1 = acc[f][g][2 * r + 1] * s + sh;
                if (sg) {
                    v0 = 0.5f * fast_tanh(0.5f * v0) + 0.5f;
                    v1 = 0.5f * fast_tanh(0.5f * v1) + 0.5f;
                } else {
                    v0 = fast_tanh(v0);
                    v1 = fast_tanh(v1);
                }
                *reinterpret_cast<float2*>(orow + (hBase + h2) * WW + wBase + w2)
                    = make_float2(v0, v1);
            }
        }
}

// ---------------- SRU scan over depth ----------------
__global__ void sru_scan_kernel(float* __restrict__ out)
{
    const int idx = blockIdx.x * blockDim.x + threadIdx.x;
    if (idx >= CIN * HW) return;
    const int c = idx / HW;
    const int hw = idx % HW;

    const float* pw = g_gates + (size_t)(0 * 64 + c) * DHW + hw;
    const float* pf = g_gates + (size_t)(1 * 64 + c) * DHW + hw;
    const float* pr = g_gates + (size_t)(2 * 64 + c) * DHW + hw;
    const float* px = g_gates + (size_t)(3 * 64 + c) * DHW + hw;
    float* po = out + (size_t)c * DHW + hw;

    float f = pf[0], r = pr[0], xx = px[0];
    float C = 1.0f - f;
    po[0] = r * C + (1.0f - r) * xx;

    for (int dd = 1; dd < DD; ++dd) {
        const int off = dd * HW;
        const float wv = pw[off];
        f = pf[off]; r = pr[off]; xx = px[off];
        C = f * C + (1.0f - f) * wv;
        po[off] = r * C + (1.0f - r) * xx;
    }
}

extern "C" void kernel_launch(void* const* d_in, const int* in_sizes, int n_in,
                              void* d_out, int out_size)
{
    const float* x     = (const float*)d_in[0];
    const float* w     = (const float*)d_in[1];
    const float* gamma = (const float*)d_in[2];
    const float* beta  = (const float*)d_in[3];
    const float* mean  = (const float*)d_in[4];
    const float* var   = (const float*)d_in[5];
    float* out = (float*)d_out;

    const size_t xt_vec = ((size_t)XT_ROWS * 128) / 16;
    zero_xt_kernel<<<(int)((xt_vec + 255) / 256), 256>>>();
    transpose_x_kernel<<<dim3(HH, DD), 128>>>(x);
    repack_kernel<<<64, 256>>>(w);

    cudaFuncSetAttribute(conv_mma_kernel,
                         cudaFuncAttributeMaxDynamicSharedMemorySize, SMEM_TOTAL);
    dim3 grid(36, 31, 2);    // (12 h-tiles x 3 w-tiles), d, cout-groups
    conv_mma_kernel<<<grid, 256, SMEM_TOTAL>>>(gamma, beta, mean, var);

    const int scan_threads = 256;
    const int scan_blocks = (CIN * HW + scan_threads - 1) / scan_threads;
    sru_scan_kernel<<<scan_blocks, scan_threads>>>(out);
}

// round 10
// speedup vs baseline: 1.0483x; 1.0483x over previous
#include <cuda_runtime.h>
#include <cuda_fp16.h>
#include <cstdint>
#include <math.h>

#define CIN 64
#define COUT 256
#define DD 31
#define HH 96
#define WW 96
#define HW (HH*WW)
#define DHW (DD*HW)
#define EPS 1e-5f

#define BH 8
#define BW 32

// padded transposed x: [33][98] planes of [8 ci-chunk][104 w][16B]
#define XT_D 33
#define XT_H 98
#define XT_W 104
#define PLANE_BYTES (8*XT_W*16)          // 13312
__device__ __half g_xt[(size_t)XT_D * XT_H * PLANE_BYTES / 2];

__device__ float  g_gates[(size_t)COUT * DHW];   // activated gates [cout][d][h][w]
// weights: [tap][2 coutgroup][8 ci-chunk][128 cout][8 ci] fp16 -> 16KB per (tap,group)
__device__ __half g_wth[27 * COUT * CIN];

// smem: A 5-stage ring of 16KB, then B [8 chunk][1020 row][16B]
#define SMA_BYTES 16384
#define NSTAGE 5
#define SMB_OFF (NSTAGE*SMA_BYTES)               // 81920
#define B_CHUNK_STRIDE (1020*16)                 // 16320
#define SMEM_TOTAL (SMB_OFF + 8*B_CHUNK_STRIDE)  // 212480

__device__ __forceinline__ uint32_t cvta_s(const void* p) {
    uint32_t a;
    asm("{ .reg .u64 t; cvta.to.shared.u64 t, %1; cvt.u32.u64 %0, t; }" : "=r"(a) : "l"(p));
    return a;
}
__device__ __forceinline__ float fast_tanh(float x) {
    float y; asm("tanh.approx.f32 %0, %1;" : "=f"(y) : "f"(x)); return y;
}
__device__ __forceinline__ void ldsm_x4(uint32_t& r0, uint32_t& r1, uint32_t& r2, uint32_t& r3,
                                        uint32_t addr) {
    asm volatile("ldmatrix.sync.aligned.m8n8.x4.shared.b16 {%0,%1,%2,%3}, [%4];"
        : "=r"(r0), "=r"(r1), "=r"(r2), "=r"(r3) : "r"(addr));
}
#define MBAR_INIT(mbar, count) \
    asm volatile("mbarrier.init.shared.b64 [%0], %1;" :: "r"((uint32_t)(mbar)), "r"((uint32_t)(count)) : "memory")
#define MBAR_EXPECT_TX(mbar, bytes) \
    asm volatile("mbarrier.arrive.expect_tx.shared.b64 _, [%0], %1;" \
        :: "r"((uint32_t)(mbar)), "r"((uint32_t)(bytes)) : "memory")
#define MBAR_ARRIVE(mbar) \
    asm volatile("mbarrier.arrive.shared.b64 _, [%0];" :: "r"((uint32_t)(mbar)) : "memory")
#define MBAR_WAIT(mbar, parity) do { \
    uint32_t _m = (uint32_t)(mbar); uint32_t _p = (uint32_t)(parity); uint32_t _done; \
    asm volatile("{\n\t.reg .pred p;\n\tmbarrier.try_wait.parity.acquire.cta.shared::cta.b64 p, [%1], %2;\n\tselp.b32 %0, 1, 0, p;\n\t}" \
        : "=r"(_done) : "r"(_m), "r"(_p) : "memory"); \
    if (!_done) { \
        asm volatile("{\n\t.reg .pred P1;\n\tWL_%=:\n\tmbarrier.try_wait.parity.acquire.cta.shared::cta.b64 P1, [%0], %1, 0x989680;\n\t@P1 bra.uni WD_%=;\n\tbra.uni WL_%=;\n\tWD_%=:\n\t}" \
            :: "r"(_m), "r"(_p) : "memory"); \
    } } while (0)
#define BULK_G2S(dst, src, bytes, mbar) \
    asm volatile("cp.async.bulk.shared::cluster.global.mbarrier::complete_tx::bytes [%0], [%1], %2, [%3];" \
        :: "r"((uint32_t)(dst)), "l"(src), "r"((uint32_t)(bytes)), "r"((uint32_t)(mbar)) : "memory")

// ---------------- pre-pass kernels ----------------
__global__ void zero_xt_kernel() {
    size_t i = (size_t)blockIdx.x * blockDim.x + threadIdx.x;
    float4* p = reinterpret_cast<float4*>(g_xt);
    if (i < ((size_t)XT_D * XT_H * PLANE_BYTES) / 16) p[i] = make_float4(0.f, 0.f, 0.f, 0.f);
}

// x[ci][d][h][w] f32 -> plane(d+1,h+1): [chunk][w+1][16B] fp16
__global__ void transpose_x_kernel(const float* __restrict__ x) {
    const int d = blockIdx.y, h = blockIdx.x;
    const int w = threadIdx.x;
    if (w >= WW) return;
    const float* src = x + (size_t)d * HW + h * WW + w;
    uint32_t pk[32];
#pragma unroll
    for (int j = 0; j < 32; ++j) {
        float v0 = src[(size_t)(2 * j) * DHW];
        float v1 = src[(size_t)(2 * j + 1) * DHW];
        __half2 h2 = __float22half2_rn(make_float2(v0, v1));
        pk[j] = *reinterpret_cast<uint32_t*>(&h2);
    }
    char* plane = (char*)g_xt + ((size_t)(d + 1) * XT_H + (h + 1)) * PLANE_BYTES;
#pragma unroll
    for (int c = 0; c < 8; ++c) {
        uint4 q = make_uint4(pk[c * 4], pk[c * 4 + 1], pk[c * 4 + 2], pk[c * 4 + 3]);
        *reinterpret_cast<uint4*>(plane + c * (XT_W * 16) + (w + 1) * 16) = q;
    }
}

// w[cout][cin][27] -> g_wth[tap][zg][chunk][cout_local 128][8 ci]
__global__ void repack_kernel(const float* __restrict__ w) {
    int id = blockIdx.x * blockDim.x + threadIdx.x;
    if (id >= COUT * CIN) return;
    int cout = id >> 6, cin = id & 63;
    const float* src = w + (size_t)id * 27;
    const int zg = cout >> 7, cl = cout & 127;
    const int chunk = cin >> 3, ci7 = cin & 7;
    const size_t base = ((size_t)zg * 8192) + chunk * 1024 + cl * 8 + ci7;
#pragma unroll
    for (int t = 0; t < 27; ++t)
        g_wth[(size_t)t * 16384 + base] = __float2half_rn(src[t]);
}

// ---------------- conv + BN + activation ----------------
__global__ __launch_bounds__(256, 1)
void conv_mma_kernel(const float* __restrict__ gamma, const float* __restrict__ beta,
                     const float* __restrict__ mean, const float* __restrict__ var)
{
    extern __shared__ __align__(128) char smem[];
    __shared__ __align__(8) uint64_t mbars[NSTAGE * 2 + 3];   // Ardy[5], Afree[5], B[3]
    const uint32_t smA_u = cvta_s(smem);
    const uint32_t smB_u = smA_u + SMB_OFF;
    uint32_t mbArdy[NSTAGE], mbAfree[NSTAGE], mbB[3];
#pragma unroll
    for (int i = 0; i < NSTAGE; ++i) { mbArdy[i] = cvta_s(&mbars[i]); mbAfree[i] = cvta_s(&mbars[NSTAGE + i]); }
#pragma unroll
    for (int i = 0; i < 3; ++i) mbB[i] = cvta_s(&mbars[2 * NSTAGE + i]);

    const int tid = threadIdx.x, wid = tid >> 5, lane = tid & 31;
    const int d = blockIdx.y;
    const int zg = blockIdx.z;
    const int coutBase = zg * 128;
    const int hBase = (blockIdx.x / 3) * BH, wBase = (blockIdx.x % 3) * BW;

    // A source base for this cout-group: g_wth + (tap*2 + zg)*16KB
    const char* wsrc = (const char*)g_wth + (size_t)zg * SMA_BYTES;

    const int warpM = (wid >> 2) * 64, warpN = (wid & 3) * 64;
    const int mr = lane >> 2, nc = lane & 3;
    const int matsel = lane >> 3, rl = lane & 7;
    const int mhalf = matsel & 1, khalf = matsel >> 1;

    // A addr = aBase[f] + buf*16384 + s*4096  (chunk = s*2 + khalf)
    uint32_t aBase[4];
#pragma unroll
    for (int f = 0; f < 4; ++f)
        aBase[f] = smA_u + khalf * 2048 + (warpM + 16 * f + mhalf * 8 + rl) * 16;
    // B addr = bBase[g2] + broff*16 + s*32640  (chunk = s*2 + khalf)
    uint32_t bBase[4];
#pragma unroll
    for (int g2 = 0; g2 < 4; ++g2) {
        int n = warpN + g2 * 16 + mhalf * 8 + rl;
        bBase[g2] = smB_u + khalf * B_CHUNK_STRIDE + ((n >> 5) * 34 + (n & 31)) * 16;
    }

    if (tid == 0) {
#pragma unroll
        for (int i = 0; i < NSTAGE; ++i) { MBAR_INIT(mbArdy[i], 1); MBAR_INIT(mbAfree[i], 8); }
#pragma unroll
        for (int i = 0; i < 3; ++i) MBAR_INIT(mbB[i], 1);
    }
    __syncthreads();
    if (tid == 0) {
#pragma unroll
        for (int i = 0; i < 3; ++i) MBAR_EXPECT_TX(mbB[i], 80u * 544u);
    }
    __syncthreads();   // expects visible before any copy issues

    // ---- B: 240 copies of 544B, one per thread (dzl, he, chunk)
    if (tid < 240) {
        const int dzl = tid / 80, r2 = tid % 80;
        const int he = r2 / 8, chunk = r2 % 8;
        const char* src = (const char*)g_xt
            + ((size_t)(d + dzl) * XT_H + hBase + he) * PLANE_BYTES
            + chunk * (XT_W * 16) + wBase * 16;
        BULK_G2S(smB_u + chunk * B_CHUNK_STRIDE + (dzl * 340 + he * 34) * 16,
                 src, 544u, mbB[dzl]);
    }
    // ---- A taps 0..4
    if (tid == 0) {
#pragma unroll
        for (int t = 0; t < NSTAGE; ++t) {
            MBAR_EXPECT_TX(mbArdy[t], SMA_BYTES);
            BULK_G2S(smA_u + t * SMA_BYTES, wsrc + (size_t)t * 2 * SMA_BYTES,
                     SMA_BYTES, mbArdy[t]);
        }
    }

    float acc[4][8][4];
#pragma unroll
    for (int f = 0; f < 4; ++f)
#pragma unroll
        for (int g = 0; g < 8; ++g)
#pragma unroll
            for (int c = 0; c < 4; ++c) acc[f][g][c] = 0.0f;

    for (int tap = 0; tap < 27; ++tap) {
        const int kd = tap / 9, kh = (tap / 3) % 3, kw = tap % 3;
        if (kh == 0 && kw == 0) { MBAR_WAIT(mbB[kd], 0); }
        const int buf = tap % NSTAGE;
        MBAR_WAIT(mbArdy[buf], (tap / NSTAGE) & 1);

        const uint32_t aOff = (uint32_t)buf * SMA_BYTES;
        const uint32_t bOff = (uint32_t)(kd * 340 + kh * 34 + kw) * 16;
#pragma unroll
        for (int s = 0; s < 4; ++s) {
            uint32_t a[4][4];
#pragma unroll
            for (int f = 0; f < 4; ++f)
                ldsm_x4(a[f][0], a[f][1], a[f][2], a[f][3],
                        aBase[f] + aOff + s * 4096);
            uint32_t b[8][2];
#pragma unroll
            for (int g2 = 0; g2 < 4; ++g2)
                ldsm_x4(b[2 * g2][0], b[2 * g2 + 1][0],
                        b[2 * g2][1], b[2 * g2 + 1][1],
                        bBase[g2] + bOff + s * 32640);
#pragma unroll
            for (int f = 0; f < 4; ++f)
#pragma unroll
                for (int g = 0; g < 8; ++g) {
                    asm volatile(
                        "mma.sync.aligned.m16n8k16.row.col.f32.f16.f16.f32 "
                        "{%0,%1,%2,%3}, {%4,%5,%6,%7}, {%8,%9}, {%0,%1,%2,%3};"
                        : "+f"(acc[f][g][0]), "+f"(acc[f][g][1]),
                          "+f"(acc[f][g][2]), "+f"(acc[f][g][3])
                        : "r"(a[f][0]), "r"(a[f][1]), "r"(a[f][2]), "r"(a[f][3]),
                          "r"(b[g][0]), "r"(b[g][1]));
                }
        }
        if (lane == 0) MBAR_ARRIVE(mbAfree[buf]);
        if (tid == 0) {
            const int nt = tap + NSTAGE;
            if (nt < 27) {
                const int nb = nt % NSTAGE;
                MBAR_WAIT(mbAfree[nb], (nt / NSTAGE - 1) & 1);
                MBAR_EXPECT_TX(mbArdy[nb], SMA_BYTES);
                BULK_G2S(smA_u + nb * SMA_BYTES,
                         wsrc + (size_t)nt * 2 * SMA_BYTES, SMA_BYTES, mbArdy[nb]);
            }
        }
    }

    // ---- epilogue: BN + activation + STG (float2)
#pragma unroll
    for (int f = 0; f < 4; ++f)
#pragma unroll
        for (int r = 0; r < 2; ++r) {
            const int cg = coutBase + warpM + 16 * f + 8 * r + mr;
            const float s = gamma[cg] * rsqrtf(var[cg] + EPS);
            const float sh = beta[cg] - mean[cg] * s;
            const int gt = cg >> 6;
            const bool sg = (gt == 1) || (gt == 2);
            float* orow = g_gates + (size_t)cg * DHW + (size_t)d * HW;
#pragma unroll
            for (int g = 0; g < 8; ++g) {
                const int n0 = warpN + 8 * g + 2 * nc;
                const int h2 = n0 >> 5, w2 = n0 & 31;
                float v0 = acc[f][g][2 * r + 0] * s + sh;
                float v1 = acc[f][g][2 * r + 1] * s + sh;
                if (sg) {
                    v0 = 0.5f * fast_tanh(0.5f * v0) + 0.5f;
                    v1 = 0.5f * fast_tanh(0.5f * v1) + 0.5f;
                } else {
                    v0 = fast_tanh(v0);
                    v1 = fast_tanh(v1);
                }
                *reinterpret_cast<float2*>(orow + (hBase + h2) * WW + wBase + w2)
                    = make_float2(v0, v1);
            }
        }
}

// ---------------- SRU scan over depth ----------------
__global__ void sru_scan_kernel(float* __restrict__ out)
{
    const int idx = blockIdx.x * blockDim.x + threadIdx.x;
    if (idx >= CIN * HW) return;
    const int c = idx / HW;
    const int hw = idx % HW;

    const float* pw = g_gates + (size_t)(0 * 64 + c) * DHW + hw;
    const float* pf = g_gates + (size_t)(1 * 64 + c) * DHW + hw;
    const float* pr = g_gates + (size_t)(2 * 64 + c) * DHW + hw;
    const float* px = g_gates + (size_t)(3 * 64 + c) * DHW + hw;
    float* po = out + (size_t)c * DHW + hw;

    float f = pf[0], r = pr[0], xx = px[0];
    float C = 1.0f - f;
    po[0] = r * C + (1.0f - r) * xx;

    for (int dd = 1; dd < DD; ++dd) {
        const int off = dd * HW;
        const float wv = pw[off];
        f = pf[off]; r = pr[off]; xx = px[off];
        C = f * C + (1.0f - f) * wv;
        po[off] = r * C + (1.0f - r) * xx;
    }
}

extern "C" void kernel_launch(void* const* d_in, const int* in_sizes, int n_in,
                              void* d_out, int out_size)
{
    const float* x     = (const float*)d_in[0];
    const float* w     = (const float*)d_in[1];
    const float* gamma = (const float*)d_in[2];
    const float* beta  = (const float*)d_in[3];
    const float* mean  = (const float*)d_in[4];
    const float* var   = (const float*)d_in[5];
    float* out = (float*)d_out;

    const size_t xt_vec = ((size_t)XT_D * XT_H * PLANE_BYTES) / 16;
    zero_xt_kernel<<<(int)((xt_vec + 255) / 256), 256>>>();
    transpose_x_kernel<<<dim3(HH, DD), 128>>>(x);
    repack_kernel<<<64, 256>>>(w);

    cudaFuncSetAttribute(conv_mma_kernel,
                         cudaFuncAttributeMaxDynamicSharedMemorySize, SMEM_TOTAL);
    dim3 grid(36, 31, 2);    // (12 h-tiles x 3 w-tiles), d, cout-groups
    conv_mma_kernel<<<grid, 256, SMEM_TOTAL>>>(gamma, beta, mean, var);

    const int scan_threads = 256;
    const int scan_blocks = (CIN * HW + scan_threads - 1) / scan_threads;
    sru_scan_kernel<<<scan_blocks, scan_threads>>>(out);
}

// round 11
// speedup vs baseline: 1.1036x; 1.0527x over previous
#include <cuda_runtime.h>
#include <cuda_fp16.h>
#include <cstdint>
#include <math.h>

#define CIN 64
#define COUT 256
#define DD 31
#define HH 96
#define WW 96
#define HW (HH*WW)
#define DHW (DD*HW)
#define EPS 1e-5f

#define BH 4
#define BW 32

// padded transposed x: [33][98] planes of [8 ci-chunk][104 w][16B]
#define XT_D 33
#define XT_H 98
#define XT_W 104
#define PLANE_BYTES (8*XT_W*16)          // 13312
__device__ __half g_xt[(size_t)XT_D * XT_H * PLANE_BYTES / 2];

__device__ float  g_gates[(size_t)COUT * DHW];   // activated gates [cout][d][h][w]
// weights: [tap][2 coutgroup][8 ci-chunk][128 cout][8 ci] fp16 -> 16KB per (tap,group)
__device__ __half g_wth[27 * COUT * CIN];

// smem: A 2-stage ring of 16KB, then B [8 chunk][612 row][16B]
#define SMA_BYTES 16384
#define NSTAGE 2
#define SMB_OFF (NSTAGE*SMA_BYTES)               // 32768
#define B_ROWS 612                               // 3 dz * 6 he * 34 we
#define B_CHUNK_STRIDE (B_ROWS*16)               // 9792
#define SMEM_TOTAL (SMB_OFF + 8*B_CHUNK_STRIDE)  // 111104 (108.5 KB) -> 2 CTAs/SM

__device__ __forceinline__ uint32_t cvta_s(const void* p) {
    uint32_t a;
    asm("{ .reg .u64 t; cvta.to.shared.u64 t, %1; cvt.u32.u64 %0, t; }" : "=r"(a) : "l"(p));
    return a;
}
__device__ __forceinline__ float fast_tanh(float x) {
    float y; asm("tanh.approx.f32 %0, %1;" : "=f"(y) : "f"(x)); return y;
}
__device__ __forceinline__ void ldsm_x4(uint32_t& r0, uint32_t& r1, uint32_t& r2, uint32_t& r3,
                                        uint32_t addr) {
    asm volatile("ldmatrix.sync.aligned.m8n8.x4.shared.b16 {%0,%1,%2,%3}, [%4];"
        : "=r"(r0), "=r"(r1), "=r"(r2), "=r"(r3) : "r"(addr));
}
#define MBAR_INIT(mbar, count) \
    asm volatile("mbarrier.init.shared.b64 [%0], %1;" :: "r"((uint32_t)(mbar)), "r"((uint32_t)(count)) : "memory")
#define MBAR_EXPECT_TX(mbar, bytes) \
    asm volatile("mbarrier.arrive.expect_tx.shared.b64 _, [%0], %1;" \
        :: "r"((uint32_t)(mbar)), "r"((uint32_t)(bytes)) : "memory")
#define MBAR_ARRIVE(mbar) \
    asm volatile("mbarrier.arrive.shared.b64 _, [%0];" :: "r"((uint32_t)(mbar)) : "memory")
#define MBAR_WAIT(mbar, parity) do { \
    uint32_t _m = (uint32_t)(mbar); uint32_t _p = (uint32_t)(parity); uint32_t _done; \
    asm volatile("{\n\t.reg .pred p;\n\tmbarrier.try_wait.parity.acquire.cta.shared::cta.b64 p, [%1], %2;\n\tselp.b32 %0, 1, 0, p;\n\t}" \
        : "=r"(_done) : "r"(_m), "r"(_p) : "memory"); \
    if (!_done) { \
        asm volatile("{\n\t.reg .pred P1;\n\tWL_%=:\n\tmbarrier.try_wait.parity.acquire.cta.shared::cta.b64 P1, [%0], %1, 0x989680;\n\t@P1 bra.uni WD_%=;\n\tbra.uni WL_%=;\n\tWD_%=:\n\t}" \
            :: "r"(_m), "r"(_p) : "memory"); \
    } } while (0)
#define BULK_G2S(dst, src, bytes, mbar) \
    asm volatile("cp.async.bulk.shared::cluster.global.mbarrier::complete_tx::bytes [%0], [%1], %2, [%3];" \
        :: "r"((uint32_t)(dst)), "l"(src), "r"((uint32_t)(bytes)), "r"((uint32_t)(mbar)) : "memory")

// ---------------- pre-pass kernels ----------------
__global__ void zero_xt_kernel() {
    size_t i = (size_t)blockIdx.x * blockDim.x + threadIdx.x;
    float4* p = reinterpret_cast<float4*>(g_xt);
    if (i < ((size_t)XT_D * XT_H * PLANE_BYTES) / 16) p[i] = make_float4(0.f, 0.f, 0.f, 0.f);
}

// x[ci][d][h][w] f32 -> plane(d+1,h+1): [chunk][w+1][16B] fp16
__global__ void transpose_x_kernel(const float* __restrict__ x) {
    const int d = blockIdx.y, h = blockIdx.x;
    const int w = threadIdx.x;
    if (w >= WW) return;
    const float* src = x + (size_t)d * HW + h * WW + w;
    uint32_t pk[32];
#pragma unroll
    for (int j = 0; j < 32; ++j) {
        float v0 = src[(size_t)(2 * j) * DHW];
        float v1 = src[(size_t)(2 * j + 1) * DHW];
        __half2 h2 = __float22half2_rn(make_float2(v0, v1));
        pk[j] = *reinterpret_cast<uint32_t*>(&h2);
    }
    char* plane = (char*)g_xt + ((size_t)(d + 1) * XT_H + (h + 1)) * PLANE_BYTES;
#pragma unroll
    for (int c = 0; c < 8; ++c) {
        uint4 q = make_uint4(pk[c * 4], pk[c * 4 + 1], pk[c * 4 + 2], pk[c * 4 + 3]);
        *reinterpret_cast<uint4*>(plane + c * (XT_W * 16) + (w + 1) * 16) = q;
    }
}

// w[cout][cin][27] -> g_wth[tap][zg][chunk][cout_local 128][8 ci]
__global__ void repack_kernel(const float* __restrict__ w) {
    int id = blockIdx.x * blockDim.x + threadIdx.x;
    if (id >= COUT * CIN) return;
    int cout = id >> 6, cin = id & 63;
    const float* src = w + (size_t)id * 27;
    const int zg = cout >> 7, cl = cout & 127;
    const int chunk = cin >> 3, ci7 = cin & 7;
    const size_t base = ((size_t)zg * 8192) + chunk * 1024 + cl * 8 + ci7;
#pragma unroll
    for (int t = 0; t < 27; ++t)
        g_wth[(size_t)t * 16384 + base] = __float2half_rn(src[t]);
}

// ---------------- conv + BN + activation ----------------
__global__ __launch_bounds__(256, 2)
void conv_mma_kernel(const float* __restrict__ gamma, const float* __restrict__ beta,
                     const float* __restrict__ mean, const float* __restrict__ var)
{
    extern __shared__ __align__(128) char smem[];
    __shared__ __align__(8) uint64_t mbars[NSTAGE * 2 + 3];   // Ardy[2], Afree[2], B[3]
    const uint32_t smA_u = cvta_s(smem);
    const uint32_t smB_u = smA_u + SMB_OFF;
    uint32_t mbArdy[NSTAGE], mbAfree[NSTAGE], mbB[3];
#pragma unroll
    for (int i = 0; i < NSTAGE; ++i) { mbArdy[i] = cvta_s(&mbars[i]); mbAfree[i] = cvta_s(&mbars[NSTAGE + i]); }
#pragma unroll
    for (int i = 0; i < 3; ++i) mbB[i] = cvta_s(&mbars[2 * NSTAGE + i]);

    const int tid = threadIdx.x, wid = tid >> 5, lane = tid & 31;
    const int d = blockIdx.y;
    const int zg = blockIdx.z;
    const int coutBase = zg * 128;
    const int hBase = (blockIdx.x / 3) * BH, wBase = (blockIdx.x % 3) * BW;

    // A source base for this cout-group: g_wth + (tap*2 + zg)*16KB
    const char* wsrc = (const char*)g_wth + (size_t)zg * SMA_BYTES;

    // 8 warps: 4 along M (32 each), 2 along N (64 each)
    const int warpM = (wid >> 1) * 32, warpN = (wid & 1) * 64;
    const int mr = lane >> 2, nc = lane & 3;
    const int matsel = lane >> 3, rl = lane & 7;
    const int mhalf = matsel & 1, khalf = matsel >> 1;

    // A addr = aBase[f] + buf*16384 + s*4096  (chunk = s*2 + khalf)
    uint32_t aBase[2];
#pragma unroll
    for (int f = 0; f < 2; ++f)
        aBase[f] = smA_u + khalf * 2048 + (warpM + 16 * f + mhalf * 8 + rl) * 16;
    // B addr = bBase[g2] + broff*16 + s*(2*B_CHUNK_STRIDE)
    uint32_t bBase[4];
#pragma unroll
    for (int g2 = 0; g2 < 4; ++g2) {
        int n = warpN + g2 * 16 + mhalf * 8 + rl;
        bBase[g2] = smB_u + khalf * B_CHUNK_STRIDE + ((n >> 5) * 34 + (n & 31)) * 16;
    }

    if (tid == 0) {
#pragma unroll
        for (int i = 0; i < NSTAGE; ++i) { MBAR_INIT(mbArdy[i], 1); MBAR_INIT(mbAfree[i], 8); }
#pragma unroll
        for (int i = 0; i < 3; ++i) MBAR_INIT(mbB[i], 1);
    }
    __syncthreads();
    if (tid == 0) {
#pragma unroll
        for (int i = 0; i < 3; ++i) MBAR_EXPECT_TX(mbB[i], 48u * 544u);
    }
    __syncthreads();   // expects visible before any copy issues

    // ---- B: 144 copies of 544B, one per thread (dzl, he, chunk)
    if (tid < 144) {
        const int dzl = tid / 48, r2 = tid % 48;
        const int he = r2 / 8, chunk = r2 % 8;
        const char* src = (const char*)g_xt
            + ((size_t)(d + dzl) * XT_H + hBase + he) * PLANE_BYTES
            + chunk * (XT_W * 16) + wBase * 16;
        BULK_G2S(smB_u + chunk * B_CHUNK_STRIDE + (dzl * 204 + he * 34) * 16,
                 src, 544u, mbB[dzl]);
    }
    // ---- A taps 0..1
    if (tid == 0) {
#pragma unroll
        for (int t = 0; t < NSTAGE; ++t) {
            MBAR_EXPECT_TX(mbArdy[t], SMA_BYTES);
            BULK_G2S(smA_u + t * SMA_BYTES, wsrc + (size_t)t * 2 * SMA_BYTES,
                     SMA_BYTES, mbArdy[t]);
        }
    }

    float acc[2][8][4];
#pragma unroll
    for (int f = 0; f < 2; ++f)
#pragma unroll
        for (int g = 0; g < 8; ++g)
#pragma unroll
            for (int c = 0; c < 4; ++c) acc[f][g][c] = 0.0f;

    for (int tap = 0; tap < 27; ++tap) {
        const int kd = tap / 9, kh = (tap / 3) % 3, kw = tap % 3;
        if (kh == 0 && kw == 0) { MBAR_WAIT(mbB[kd], 0); }
        const int buf = tap % NSTAGE;
        MBAR_WAIT(mbArdy[buf], (tap / NSTAGE) & 1);

        const uint32_t aOff = (uint32_t)buf * SMA_BYTES;
        const uint32_t bOff = (uint32_t)(kd * 204 + kh * 34 + kw) * 16;
#pragma unroll
        for (int s = 0; s < 4; ++s) {
            uint32_t a[2][4];
#pragma unroll
            for (int f = 0; f < 2; ++f)
                ldsm_x4(a[f][0], a[f][1], a[f][2], a[f][3],
                        aBase[f] + aOff + s * 4096);
            uint32_t b[8][2];
#pragma unroll
            for (int g2 = 0; g2 < 4; ++g2)
                ldsm_x4(b[2 * g2][0], b[2 * g2 + 1][0],
                        b[2 * g2][1], b[2 * g2 + 1][1],
                        bBase[g2] + bOff + s * (2 * B_CHUNK_STRIDE));
#pragma unroll
            for (int f = 0; f < 2; ++f)
#pragma unroll
                for (int g = 0; g < 8; ++g) {
                    asm volatile(
                        "mma.sync.aligned.m16n8k16.row.col.f32.f16.f16.f32 "
                        "{%0,%1,%2,%3}, {%4,%5,%6,%7}, {%8,%9}, {%0,%1,%2,%3};"
                        : "+f"(acc[f][g][0]), "+f"(acc[f][g][1]),
                          "+f"(acc[f][g][2]), "+f"(acc[f][g][3])
                        : "r"(a[f][0]), "r"(a[f][1]), "r"(a[f][2]), "r"(a[f][3]),
                          "r"(b[g][0]), "r"(b[g][1]));
                }
        }
        if (lane == 0) MBAR_ARRIVE(mbAfree[buf]);
        if (tid == 0) {
            const int nt = tap + NSTAGE;
            if (nt < 27) {
                const int nb = nt % NSTAGE;
                MBAR_WAIT(mbAfree[nb], (nt / NSTAGE - 1) & 1);
                MBAR_EXPECT_TX(mbArdy[nb], SMA_BYTES);
                BULK_G2S(smA_u + nb * SMA_BYTES,
                         wsrc + (size_t)nt * 2 * SMA_BYTES, SMA_BYTES, mbArdy[nb]);
            }
        }
    }

    // ---- epilogue: BN + activation + STG (float2)
#pragma unroll
    for (int f = 0; f < 2; ++f)
#pragma unroll
        for (int r = 0; r < 2; ++r) {
            const int cg = coutBase + warpM + 16 * f + 8 * r + mr;
            const float s = gamma[cg] * rsqrtf(var[cg] + EPS);
            const float sh = beta[cg] - mean[cg] * s;
            const int gt = cg >> 6;
            const bool sg = (gt == 1) || (gt == 2);
            float* orow = g_gates + (size_t)cg * DHW + (size_t)d * HW;
#pragma unroll
            for (int g = 0; g < 8; ++g) {
                const int n0 = warpN + 8 * g + 2 * nc;
                const int h2 = n0 >> 5, w2 = n0 & 31;
                float v0 = acc[f][g][2 * r + 0] * s + sh;
                float v1 = acc[f][g][2 * r + 1] * s + sh;
                if (sg) {
                    v0 = 0.5f * fast_tanh(0.5f * v0) + 0.5f;
                    v1 = 0.5f * fast_tanh(0.5f * v1) + 0.5f;
                } else {
                    v0 = fast_tanh(v0);
                    v1 = fast_tanh(v1);
                }
                *reinterpret_cast<float2*>(orow + (hBase + h2) * WW + wBase + w2)
                    = make_float2(v0, v1);
            }
        }
}

// ---------------- SRU scan over depth ----------------
__global__ void sru_scan_kernel(float* __restrict__ out)
{
    const int idx = blockIdx.x * blockDim.x + threadIdx.x;
    if (idx >= CIN * HW) return;
    const int c = idx / HW;
    const int hw = idx % HW;

    const float* pw = g_gates + (size_t)(0 * 64 + c) * DHW + hw;
    const float* pf = g_gates + (size_t)(1 * 64 + c) * DHW + hw;
    const float* pr = g_gates + (size_t)(2 * 64 + c) * DHW + hw;
    const float* px = g_gates + (size_t)(3 * 64 + c) * DHW + hw;
    float* po = out + (size_t)c * DHW + hw;

    float f = pf[0], r = pr[0], xx = px[0];
    float C = 1.0f - f;
    po[0] = r * C + (1.0f - r) * xx;

    for (int dd = 1; dd < DD; ++dd) {
        const int off = dd * HW;
        const float wv = pw[off];
        f = pf[off]; r = pr[off]; xx = px[off];
        C = f * C + (1.0f - f) * wv;
        po[off] = r * C + (1.0f - r) * xx;
    }
}

extern "C" void kernel_launch(void* const* d_in, const int* in_sizes, int n_in,
                              void* d_out, int out_size)
{
    const float* x     = (const float*)d_in[0];
    const float* w     = (const float*)d_in[1];
    const float* gamma = (const float*)d_in[2];
    const float* beta  = (const float*)d_in[3];
    const float* mean  = (const float*)d_in[4];
    const float* var   = (const float*)d_in[5];
    float* out = (float*)d_out;

    const size_t xt_vec = ((size_t)XT_D * XT_H * PLANE_BYTES) / 16;
    zero_xt_kernel<<<(int)((xt_vec + 255) / 256), 256>>>();
    transpose_x_kernel<<<dim3(HH, DD), 128>>>(x);
    repack_kernel<<<64, 256>>>(w);

    cudaFuncSetAttribute(conv_mma_kernel,
                         cudaFuncAttributeMaxDynamicSharedMemorySize, SMEM_TOTAL);
    dim3 grid(72, 31, 2);    // (24 h-tiles x 3 w-tiles), d, cout-groups
    conv_mma_kernel<<<grid, 256, SMEM_TOTAL>>>(gamma, beta, mean, var);

    const int scan_threads = 256;
    const int scan_blocks = (CIN * HW + scan_threads - 1) / scan_threads;
    sru_scan_kernel<<<scan_blocks, scan_threads>>>(out);
}